// round 13
// baseline (speedup 1.0000x reference)
#include <cuda_runtime.h>
#include <cstdint>

#define FFTC 256
#define NL 11
#define TT 2048
#define NCTA 16
#define SPS 12                       // stages/step: s=0..10 layer-partial publishes; s=11 logits partials
#define NSLOT 32                     // flag slot ring (>= in-flight stage window, power of 2)
#define MEMCOLS 2047                 // sum of dilations 1+2+...+1024

// Persistent state (recomputed every kernel_launch for determinism)
__device__ float g_ring[(size_t)NCTA*MEMCOLS*FFTC]; // PRIVATE ring buffer per CTA
__device__ float g_cond[NL*16*FFTC];                // cond projections per (layer, frame)
__device__ float g_emb[256*FFTC];                   // tanh(emb_raw)
__device__ float g_part[12*NCTA*FFTC];              // per-layer (+logits) partial z vectors
__device__ unsigned g_flags[NSLOT*32];              // per-stage slot: 16 per-CTA words + pad (128B)

// Per-CTA release store: no atomic RMW, no LTS serialization across CTAs.
__device__ __forceinline__ void signal_stage(int idx, int blk){
  const unsigned val = (unsigned)(idx + 1);          // monotone stage counter
  asm volatile("st.release.gpu.global.u32 [%0], %1;"
               :: "l"(g_flags + (idx & (NSLOT-1))*32 + blk), "r"(val) : "memory");
}
// Poll: min over the 16 per-CTA words must reach idx+1.
__device__ __forceinline__ void wait_stage(int idx){
  const unsigned val = (unsigned)(idx + 1);
  const unsigned* p = g_flags + (idx & (NSLOT-1))*32;
  for(;;){
    unsigned m = 0xffffffffu;
    #pragma unroll
    for (int k=0;k<NCTA;k++){
      unsigned v;
      asm volatile("ld.acquire.gpu.global.u32 %0, [%1];" : "=r"(v) : "l"(p + k) : "memory");
      m = min(m, v);
    }
    if (m >= val) break;
  }
}

// 8-float (32B) weight load: read-only, keep resident in L2 (evict_last).
struct F8 { float f[8]; };
__device__ __forceinline__ F8 ldnc8(const float* p){
  unsigned long long a,b,c,d;
  asm volatile("ld.global.nc.L2::evict_last.v4.b64 {%0,%1,%2,%3}, [%4];"
               : "=l"(a), "=l"(b), "=l"(c), "=l"(d) : "l"(p));
  F8 r;
  r.f[0] = __uint_as_float((unsigned)(a));        r.f[1] = __uint_as_float((unsigned)(a>>32));
  r.f[2] = __uint_as_float((unsigned)(b));        r.f[3] = __uint_as_float((unsigned)(b>>32));
  r.f[4] = __uint_as_float((unsigned)(c));        r.f[5] = __uint_as_float((unsigned)(c>>32));
  r.f[6] = __uint_as_float((unsigned)(d));        r.f[7] = __uint_as_float((unsigned)(d>>32));
  return r;
}
// cross-CTA data: bypass L1 (L2 is the coherence point)
__device__ __forceinline__ float ldcg(const float* p){
  float v;
  asm volatile("ld.global.cg.f32 %0, [%1];" : "=f"(v) : "l"(p));
  return v;
}

__device__ __forceinline__ float dot8(const F8& w, const float* v, float p){
  #pragma unroll
  for (int k=0;k<8;k++) p = fmaf(w.f[k], v[k], p);
  return p;
}
__device__ __forceinline__ float red32(float p){
  #pragma unroll
  for (int k=16;k>0;k>>=1) p += __shfl_xor_sync(0xffffffffu, p, k);
  return p;
}

// ---------------- init + precompute fused ----------------
__global__ void init_all(const float* __restrict__ y,
                         const float* __restrict__ emb_raw,
                         const float* __restrict__ condW){
  const int b = blockIdx.x, tid = threadIdx.x;
  if (b < 256) {
    g_emb[b*256 + tid] = tanhf(emb_raw[b*256 + tid]);
  } else if (b < 256 + NL*16) {
    int b2 = b - 256;
    int j = b2 >> 4, f = b2 & 15;
    int row = j*256 + tid;
    float acc = 0.0f;
    #pragma unroll
    for (int c=0; c<80; c++) acc = fmaf(condW[row*80 + c], y[c*16 + f], acc);
    g_cond[(j*16 + f)*256 + tid] = acc;
  }
  size_t i = (size_t)b*blockDim.x + tid;
  size_t stride = (size_t)gridDim.x*blockDim.x;
  for (size_t k=i; k<(size_t)NCTA*MEMCOLS*FFTC; k+=stride) g_ring[k] = 0.0f;
  for (size_t k=i; k<(size_t)NSLOT*32; k+=stride) g_flags[k] = 0u;
}

// ---------------- main persistent kernel: 16 CTAs x 512 threads ----------------
// Stage A: warp-per-h-row (16 warps = 16 rows/CTA), 8 floats/lane, full-warp reduce.
// Partial z: zrow = tid>>1 (256 outputs), half = tid&1; 16-wide inner slice per CTA.
// One chip-wide sync per layer; x', logits and SAMPLER computed redundantly per CTA.
// Loads are ISSUED before the flag wait and CONSUMED after it.
__global__ void __launch_bounds__(512,1) fftnet_main(
  const float* __restrict__ WVp, const float* __restrict__ WVc,
  const float* __restrict__ Wow, const float* __restrict__ Wob,
  const float* __restrict__ endw, const float* __restrict__ endb,
  const float* __restrict__ samples, float* __restrict__ out)
{
  __shared__ __align__(16) float xs[FFTC];   // current x (identical in all CTAs)
  __shared__ __align__(16) float hs[16];     // this CTA's h rows
  __shared__ __align__(16) float lg[FFTC];   // logits (all CTAs)
  __shared__ __align__(16) float es[FFTC];   // staged emb row (sampler)
  __shared__ int s_sel;
  const int tid = threadIdx.x;
  const int blk = blockIdx.x;
  const int w = tid >> 5, lane = tid & 31;
  const int r = blk*16 + w;                  // h row owned by this warp
  const int zrow = tid >> 1;
  const int half = tid & 1;
  const int in0 = blk*16 + half*8;           // inner-dim base for partial z
  float* ring = g_ring + (size_t)blk*MEMCOLS*FFTC;

  if (tid < FFTC) xs[tid] = g_emb[127*FFTC + tid];
  __syncthreads();

  for (int t=0; t<TT; ++t){
    const int f = t >> 7;
    const int base = t*SPS;

    #pragma unroll 1
    for (int j=0; j<NL; ++j){
      const int col = ((1<<j) - 1) + (t & ((1<<j) - 1));
      // ---- ISSUE loads only; consume nothing until after the wait ----
      F8 wp = ldnc8(WVp + (size_t)(j*FFTC + r)*FFTC + lane*8);
      float mc[8];
      *(float4*)(mc)   = *(const float4*)(ring + col*FFTC + lane*8);
      *(float4*)(mc+4) = *(const float4*)(ring + col*FFTC + lane*8 + 4);
      F8 wc = ldnc8(WVc + (size_t)(j*FFTC + r)*FFTC + lane*8);
      F8 wo = ldnc8(Wow + (size_t)(j*FFTC + zrow)*FFTC + in0);
      float cnd = (lane==0) ? g_cond[(j*16 + f)*FFTC + r] : 0.0f;
      float wobp = (j>0 && tid<FFTC) ? Wob[(j-1)*FFTC + tid] : 0.0f;

      if (j > 0){
        if (tid==0) wait_stage(base + (j-1));         // single poller, per-CTA words
        __syncthreads();                              // wakes all warps together
        if (tid < FFTC){
          float s1 = wobp;
          const float* gp = g_part + (j-1)*NCTA*FFTC + tid;
          #pragma unroll
          for (int k=0;k<NCTA;k++) s1 += ldcg(gp + k*FFTC);
          xs[tid] = fmaxf(s1 + xs[tid], 0.0f);        // x' = relu(z + b + x)
        }
        __syncthreads();
      }
      // ---- all math after the wait (loads have had the wait to land) ----
      float part = cnd;
      part = dot8(wp, mc, part);                      // same FP order as before
      part = dot8(wc, xs + lane*8, part);
      part = red32(part);
      if (lane==0) hs[w] = fmaxf(part, 0.0f);
      __syncthreads();
      // partial z over this CTA's 16 h rows
      float pk = dot8(wo, hs + half*8, 0.0f);
      float oth = __shfl_xor_sync(0xffffffffu, pk, 1);
      float z = (half==0) ? (pk + oth) : (oth + pk);
      if (half==0) g_part[(j*NCTA + blk)*FFTC + zrow] = z;
      __syncthreads();                                // partial stores before release
      if (tid==0) signal_stage(base + j, blk);
      if (tid < FFTC) ring[col*FFTC + tid] = xs[tid]; // private, outside release drain
    }

    { // ---- logits: x' after layer 10, then partial endw slice ----
      F8 ew = ldnc8(endw + (size_t)zrow*FFTC + in0);
      float wobL = (tid<FFTC) ? Wob[10*FFTC + tid] : 0.0f;
      if (tid==0) wait_stage(base + 10);
      __syncthreads();
      if (tid < FFTC){
        float s1 = wobL;
        const float* gp = g_part + 10*NCTA*FFTC + tid;
        #pragma unroll
        for (int k=0;k<NCTA;k++) s1 += ldcg(gp + k*FFTC);
        xs[tid] = fmaxf(s1 + xs[tid], 0.0f);
      }
      __syncthreads();
      float pk = dot8(ew, xs + in0, 0.0f);
      float oth = __shfl_xor_sync(0xffffffffu, pk, 1);
      float z = (half==0) ? (pk + oth) : (oth + pk);
      if (half==0) g_part[(11*NCTA + blk)*FFTC + zrow] = z;
      __syncthreads();
      if (tid==0) signal_stage(base + 11, blk);
    }

    { // ---- sampler: ALL CTAs redundantly (deterministic); no broadcast sync ----
      float u = (tid < 32) ? samples[t] : 0.0f;       // prefetch before the wait
      if (tid==0) wait_stage(base + 11);
      __syncthreads();
      if (tid < FFTC){
        float s1 = endb[tid];
        const float* gp = g_part + 11*NCTA*FFTC + tid;
        #pragma unroll
        for (int k=0;k<NCTA;k++) s1 += ldcg(gp + k*FFTC);
        lg[tid] = s1;                                 // C_SCALE == 1
      }
      __syncthreads();
      if (tid < 32){
        float4 va = *(const float4*)(lg + lane*8);
        float4 vb = *(const float4*)(lg + lane*8 + 4);
        float v[8] = {va.x,va.y,va.z,va.w,vb.x,vb.y,vb.z,vb.w};
        float m = v[0];
        #pragma unroll
        for (int k=1;k<8;k++) m = fmaxf(m, v[k]);
        #pragma unroll
        for (int k=16;k>0;k>>=1) m = fmaxf(m, __shfl_xor_sync(0xffffffffu, m, k));
        float e[8]; float sl = 0.0f;
        #pragma unroll
        for (int k=0;k<8;k++){ e[k] = expf(v[k] - m); sl += e[k]; }
        float tot = sl;
        #pragma unroll
        for (int k=16;k>0;k>>=1) tot += __shfl_xor_sync(0xffffffffu, tot, k);
        float cs[8]; float c = 0.0f;
        #pragma unroll
        for (int k=0;k<8;k++){ c += e[k] / tot; cs[k] = c; }
        float inc = c;
        #pragma unroll
        for (int k=1;k<32;k<<=1){ float o = __shfl_up_sync(0xffffffffu, inc, k); if (lane>=k) inc += o; }
        float off = __shfl_up_sync(0xffffffffu, inc, 1);
        if (lane == 0) off = 0.0f;
        int cand = 1<<30;
        #pragma unroll
        for (int k=0;k<8;k++) if (cand == (1<<30) && (off + cs[k]) > u) cand = lane*8 + k;
        #pragma unroll
        for (int k=16;k>0;k>>=1) cand = min(cand, __shfl_xor_sync(0xffffffffu, cand, k));
        int sel = (cand >= 256) ? 0 : cand;
        if (lane == 0){
          s_sel = sel;
          if (blk == 0) out[t] = (float)sel;
        }
        // stage emb[sel] via wide evict_last loads (L2-resident emb)
        F8 er = ldnc8(g_emb + sel*FFTC + lane*8);
        #pragma unroll
        for (int k=0;k<8;k++) es[lane*8 + k] = er.f[k];
      }
      __syncthreads();
      if (tid < FFTC) xs[tid] = es[tid];              // next step's x0, locally
      __syncthreads();
    }
  }
}

extern "C" void kernel_launch(void* const* d_in, const int* in_sizes, int n_in,
                              void* d_out, int out_size) {
  // ---- Robust input binding: identify tensors by element count, not position.
  int i1280=-1, i2048=-1, i225280=-1, i2816=-1, i256=-1;
  int i65536[2] = {-1,-1}; int n65536 = 0;
  int i720[3] = {-1,-1,-1}; int n720 = 0;
  for (int i=0;i<n_in;i++){
    switch (in_sizes[i]){
      case 1280:   i1280 = i; break;
      case 2048:   i2048 = i; break;
      case 225280: i225280 = i; break;
      case 2816:   i2816 = i; break;
      case 256:    i256 = i; break;
      case 65536:  if (n65536 < 2) i65536[n65536++] = i; break;
      case 720896: if (n720 < 3) i720[n720++] = i; break;
      default: break;
    }
  }
  if (i1280<0 || i2048<0 || i225280<0 || i2816<0 || i256<0 || n65536!=2 || n720!=3){
    i1280=0; i2048=1; i65536[0]=2; i225280=3; i720[0]=4; i720[1]=5; i720[2]=6;
    i2816=7; i65536[1]=8; i256=9;
  }
  const float* y        = (const float*)d_in[i1280];     // [80,16]
  const float* samples  = (const float*)d_in[i2048];     // [2048]
  const float* condW    = (const float*)d_in[i225280];   // [2816,80]
  const float* Wob      = (const float*)d_in[i2816];     // [11,256]
  const float* endb     = (const float*)d_in[i256];      // [256]
  const float* emb_raw  = (const float*)d_in[i65536[0]]; // [256,256]
  const float* endw     = (const float*)d_in[i65536[1]]; // [256,256]
  int before = 0;
  for (int k=0;k<3;k++) if (i720[k] < i2816) before++;
  const float *WVp, *WVc, *Wow;
  if (before == 0) { Wow = (const float*)d_in[i720[0]];
                     WVp = (const float*)d_in[i720[1]];
                     WVc = (const float*)d_in[i720[2]]; }
  else             { WVp = (const float*)d_in[i720[0]];
                     WVc = (const float*)d_in[i720[1]];
                     Wow = (const float*)d_in[i720[2]]; }
  float* out = (float*)d_out;                            // [2048] sampled ids (as float32)

  init_all<<<2048,256>>>(y, emb_raw, condW);
  fftnet_main<<<NCTA,512>>>(WVp, WVc, Wow, Wob, endw, endb, samples, out);
}

// round 14
// speedup vs baseline: 2.1782x; 2.1782x over previous
#include <cuda_runtime.h>
#include <cstdint>

#define FFTC 256
#define NL 11
#define TT 2048
#define NCTA 16
#define SPS 12                       // stages/step: s=0..10 layer-partial publishes; s=11 logits partials
#define NSLOT 32                     // flag slot ring (>= in-flight stage window, power of 2)
#define MEMCOLS 2047                 // sum of dilations 1+2+...+1024

// Persistent state (recomputed every kernel_launch for determinism)
__device__ float g_ring[(size_t)NCTA*MEMCOLS*FFTC]; // PRIVATE ring buffer per CTA
__device__ float g_cond[NL*16*FFTC];                // cond projections per (layer, frame)
__device__ float g_emb[256*FFTC];                   // tanh(emb_raw)
__device__ float g_part[12*NCTA*FFTC];              // per-layer (+logits) partial z vectors
__device__ unsigned g_flags[NSLOT*32];              // per-stage slot: 16 per-CTA words + pad (128B)

// Per-CTA release store: no atomic RMW, stores from 16 CTAs commit in parallel.
__device__ __forceinline__ void signal_stage(int idx, int blk){
  const unsigned val = (unsigned)(idx + 1);          // monotone stage counter
  asm volatile("st.release.gpu.global.u32 [%0], %1;"
               :: "l"(g_flags + (idx & (NSLOT-1))*32 + blk), "r"(val) : "memory");
}
// Poll with RELAXED loads (no ordering -> all 16 overlap into one L2 round trip),
// then a single acquire fence once the condition is met.
__device__ __forceinline__ void wait_stage(int idx){
  const unsigned val = (unsigned)(idx + 1);
  const unsigned* p = g_flags + (idx & (NSLOT-1))*32;
  for(;;){
    unsigned m = 0xffffffffu;
    #pragma unroll
    for (int k=0;k<NCTA;k++){
      unsigned v;
      asm volatile("ld.relaxed.gpu.global.u32 %0, [%1];" : "=r"(v) : "l"(p + k) : "memory");
      m = min(m, v);
    }
    if (m >= val) break;
  }
  asm volatile("fence.acq_rel.gpu;" ::: "memory");   // acquire: orders subsequent g_part reads
}

// 8-float (32B) weight load: read-only, keep resident in L2 (evict_last).
struct F8 { float f[8]; };
__device__ __forceinline__ F8 ldnc8(const float* p){
  unsigned long long a,b,c,d;
  asm volatile("ld.global.nc.L2::evict_last.v4.b64 {%0,%1,%2,%3}, [%4];"
               : "=l"(a), "=l"(b), "=l"(c), "=l"(d) : "l"(p));
  F8 r;
  r.f[0] = __uint_as_float((unsigned)(a));        r.f[1] = __uint_as_float((unsigned)(a>>32));
  r.f[2] = __uint_as_float((unsigned)(b));        r.f[3] = __uint_as_float((unsigned)(b>>32));
  r.f[4] = __uint_as_float((unsigned)(c));        r.f[5] = __uint_as_float((unsigned)(c>>32));
  r.f[6] = __uint_as_float((unsigned)(d));        r.f[7] = __uint_as_float((unsigned)(d>>32));
  return r;
}
// cross-CTA data: bypass L1 (L2 is the coherence point)
__device__ __forceinline__ float ldcg(const float* p){
  float v;
  asm volatile("ld.global.cg.f32 %0, [%1];" : "=f"(v) : "l"(p));
  return v;
}

__device__ __forceinline__ float dot8(const F8& w, const float* v, float p){
  #pragma unroll
  for (int k=0;k<8;k++) p = fmaf(w.f[k], v[k], p);
  return p;
}
__device__ __forceinline__ float red32(float p){
  #pragma unroll
  for (int k=16;k>0;k>>=1) p += __shfl_xor_sync(0xffffffffu, p, k);
  return p;
}

// ---------------- init + precompute fused ----------------
__global__ void init_all(const float* __restrict__ y,
                         const float* __restrict__ emb_raw,
                         const float* __restrict__ condW){
  const int b = blockIdx.x, tid = threadIdx.x;
  if (b < 256) {
    g_emb[b*256 + tid] = tanhf(emb_raw[b*256 + tid]);
  } else if (b < 256 + NL*16) {
    int b2 = b - 256;
    int j = b2 >> 4, f = b2 & 15;
    int row = j*256 + tid;
    float acc = 0.0f;
    #pragma unroll
    for (int c=0; c<80; c++) acc = fmaf(condW[row*80 + c], y[c*16 + f], acc);
    g_cond[(j*16 + f)*256 + tid] = acc;
  }
  size_t i = (size_t)b*blockDim.x + tid;
  size_t stride = (size_t)gridDim.x*blockDim.x;
  for (size_t k=i; k<(size_t)NCTA*MEMCOLS*FFTC; k+=stride) g_ring[k] = 0.0f;
  for (size_t k=i; k<(size_t)NSLOT*32; k+=stride) g_flags[k] = 0u;
}

// ---------------- main persistent kernel: 16 CTAs x 512 threads ----------------
// Stage A: warp-per-h-row (16 warps = 16 rows/CTA), 8 floats/lane, full-warp reduce.
// Partial z: zrow = tid>>1 (256 outputs), half = tid&1; 16-wide inner slice per CTA.
// One chip-wide sync per layer; x', logits and SAMPLER computed redundantly per CTA.
// Loads are ISSUED before the flag wait and CONSUMED after it.
__global__ void __launch_bounds__(512,1) fftnet_main(
  const float* __restrict__ WVp, const float* __restrict__ WVc,
  const float* __restrict__ Wow, const float* __restrict__ Wob,
  const float* __restrict__ endw, const float* __restrict__ endb,
  const float* __restrict__ samples, float* __restrict__ out)
{
  __shared__ __align__(16) float xs[FFTC];   // current x (identical in all CTAs)
  __shared__ __align__(16) float hs[16];     // this CTA's h rows
  __shared__ __align__(16) float lg[FFTC];   // logits (all CTAs)
  __shared__ __align__(16) float es[FFTC];   // staged emb row (sampler)
  __shared__ int s_sel;
  const int tid = threadIdx.x;
  const int blk = blockIdx.x;
  const int w = tid >> 5, lane = tid & 31;
  const int r = blk*16 + w;                  // h row owned by this warp
  const int zrow = tid >> 1;
  const int half = tid & 1;
  const int in0 = blk*16 + half*8;           // inner-dim base for partial z
  float* ring = g_ring + (size_t)blk*MEMCOLS*FFTC;

  if (tid < FFTC) xs[tid] = g_emb[127*FFTC + tid];
  __syncthreads();

  for (int t=0; t<TT; ++t){
    const int f = t >> 7;
    const int base = t*SPS;

    #pragma unroll 1
    for (int j=0; j<NL; ++j){
      const int col = ((1<<j) - 1) + (t & ((1<<j) - 1));
      // ---- ISSUE loads only; consume nothing until after the wait ----
      F8 wp = ldnc8(WVp + (size_t)(j*FFTC + r)*FFTC + lane*8);
      float mc[8];
      *(float4*)(mc)   = *(const float4*)(ring + col*FFTC + lane*8);
      *(float4*)(mc+4) = *(const float4*)(ring + col*FFTC + lane*8 + 4);
      F8 wc = ldnc8(WVc + (size_t)(j*FFTC + r)*FFTC + lane*8);
      F8 wo = ldnc8(Wow + (size_t)(j*FFTC + zrow)*FFTC + in0);
      float cnd = (lane==0) ? g_cond[(j*16 + f)*FFTC + r] : 0.0f;
      float wobp = (j>0 && tid<FFTC) ? Wob[(j-1)*FFTC + tid] : 0.0f;

      if (j > 0){
        if (tid==0) wait_stage(base + (j-1));         // single poller, relaxed+fence
        __syncthreads();                              // wakes all warps together
        if (tid < FFTC){
          float s1 = wobp;
          const float* gp = g_part + (j-1)*NCTA*FFTC + tid;
          #pragma unroll
          for (int k=0;k<NCTA;k++) s1 += ldcg(gp + k*FFTC);
          xs[tid] = fmaxf(s1 + xs[tid], 0.0f);        // x' = relu(z + b + x)
        }
        __syncthreads();
      }
      // ---- all math after the wait (loads have had the wait to land) ----
      float part = cnd;
      part = dot8(wp, mc, part);                      // same FP order as before
      part = dot8(wc, xs + lane*8, part);
      part = red32(part);
      if (lane==0) hs[w] = fmaxf(part, 0.0f);
      __syncthreads();
      // partial z over this CTA's 16 h rows
      float pk = dot8(wo, hs + half*8, 0.0f);
      float oth = __shfl_xor_sync(0xffffffffu, pk, 1);
      float z = (half==0) ? (pk + oth) : (oth + pk);
      if (half==0) g_part[(j*NCTA + blk)*FFTC + zrow] = z;
      __syncthreads();                                // partial stores before release
      if (tid==0) signal_stage(base + j, blk);
      if (tid < FFTC) ring[col*FFTC + tid] = xs[tid]; // private, outside release drain
    }

    { // ---- logits: x' after layer 10, then partial endw slice ----
      F8 ew = ldnc8(endw + (size_t)zrow*FFTC + in0);
      float wobL = (tid<FFTC) ? Wob[10*FFTC + tid] : 0.0f;
      if (tid==0) wait_stage(base + 10);
      __syncthreads();
      if (tid < FFTC){
        float s1 = wobL;
        const float* gp = g_part + 10*NCTA*FFTC + tid;
        #pragma unroll
        for (int k=0;k<NCTA;k++) s1 += ldcg(gp + k*FFTC);
        xs[tid] = fmaxf(s1 + xs[tid], 0.0f);
      }
      __syncthreads();
      float pk = dot8(ew, xs + in0, 0.0f);
      float oth = __shfl_xor_sync(0xffffffffu, pk, 1);
      float z = (half==0) ? (pk + oth) : (oth + pk);
      if (half==0) g_part[(11*NCTA + blk)*FFTC + zrow] = z;
      __syncthreads();
      if (tid==0) signal_stage(base + 11, blk);
    }

    { // ---- sampler: ALL CTAs redundantly (deterministic); no broadcast sync ----
      float u = (tid < 32) ? samples[t] : 0.0f;       // prefetch before the wait
      if (tid==0) wait_stage(base + 11);
      __syncthreads();
      if (tid < FFTC){
        float s1 = endb[tid];
        const float* gp = g_part + 11*NCTA*FFTC + tid;
        #pragma unroll
        for (int k=0;k<NCTA;k++) s1 += ldcg(gp + k*FFTC);
        lg[tid] = s1;                                 // C_SCALE == 1
      }
      __syncthreads();
      if (tid < 32){
        float4 va = *(const float4*)(lg + lane*8);
        float4 vb = *(const float4*)(lg + lane*8 + 4);
        float v[8] = {va.x,va.y,va.z,va.w,vb.x,vb.y,vb.z,vb.w};
        float m = v[0];
        #pragma unroll
        for (int k=1;k<8;k++) m = fmaxf(m, v[k]);
        #pragma unroll
        for (int k=16;k>0;k>>=1) m = fmaxf(m, __shfl_xor_sync(0xffffffffu, m, k));
        float e[8]; float sl = 0.0f;
        #pragma unroll
        for (int k=0;k<8;k++){ e[k] = expf(v[k] - m); sl += e[k]; }
        float tot = sl;
        #pragma unroll
        for (int k=16;k>0;k>>=1) tot += __shfl_xor_sync(0xffffffffu, tot, k);
        float cs[8]; float c = 0.0f;
        #pragma unroll
        for (int k=0;k<8;k++){ c += e[k] / tot; cs[k] = c; }
        float inc = c;
        #pragma unroll
        for (int k=1;k<32;k<<=1){ float o = __shfl_up_sync(0xffffffffu, inc, k); if (lane>=k) inc += o; }
        float off = __shfl_up_sync(0xffffffffu, inc, 1);
        if (lane == 0) off = 0.0f;
        int cand = 1<<30;
        #pragma unroll
        for (int k=0;k<8;k++) if (cand == (1<<30) && (off + cs[k]) > u) cand = lane*8 + k;
        #pragma unroll
        for (int k=16;k>0;k>>=1) cand = min(cand, __shfl_xor_sync(0xffffffffu, cand, k));
        int sel = (cand >= 256) ? 0 : cand;
        if (lane == 0){
          s_sel = sel;
          if (blk == 0) out[t] = (float)sel;
        }
        // stage emb[sel] via wide evict_last loads (L2-resident emb)
        F8 er = ldnc8(g_emb + sel*FFTC + lane*8);
        #pragma unroll
        for (int k=0;k<8;k++) es[lane*8 + k] = er.f[k];
      }
      __syncthreads();
      if (tid < FFTC) xs[tid] = es[tid];              // next step's x0, locally
      __syncthreads();
    }
  }
}

extern "C" void kernel_launch(void* const* d_in, const int* in_sizes, int n_in,
                              void* d_out, int out_size) {
  // ---- Robust input binding: identify tensors by element count, not position.
  int i1280=-1, i2048=-1, i225280=-1, i2816=-1, i256=-1;
  int i65536[2] = {-1,-1}; int n65536 = 0;
  int i720[3] = {-1,-1,-1}; int n720 = 0;
  for (int i=0;i<n_in;i++){
    switch (in_sizes[i]){
      case 1280:   i1280 = i; break;
      case 2048:   i2048 = i; break;
      case 225280: i225280 = i; break;
      case 2816:   i2816 = i; break;
      case 256:    i256 = i; break;
      case 65536:  if (n65536 < 2) i65536[n65536++] = i; break;
      case 720896: if (n720 < 3) i720[n720++] = i; break;
      default: break;
    }
  }
  if (i1280<0 || i2048<0 || i225280<0 || i2816<0 || i256<0 || n65536!=2 || n720!=3){
    i1280=0; i2048=1; i65536[0]=2; i225280=3; i720[0]=4; i720[1]=5; i720[2]=6;
    i2816=7; i65536[1]=8; i256=9;
  }
  const float* y        = (const float*)d_in[i1280];     // [80,16]
  const float* samples  = (const float*)d_in[i2048];     // [2048]
  const float* condW    = (const float*)d_in[i225280];   // [2816,80]
  const float* Wob      = (const float*)d_in[i2816];     // [11,256]
  const float* endb     = (const float*)d_in[i256];      // [256]
  const float* emb_raw  = (const float*)d_in[i65536[0]]; // [256,256]
  const float* endw     = (const float*)d_in[i65536[1]]; // [256,256]
  int before = 0;
  for (int k=0;k<3;k++) if (i720[k] < i2816) before++;
  const float *WVp, *WVc, *Wow;
  if (before == 0) { Wow = (const float*)d_in[i720[0]];
                     WVp = (const float*)d_in[i720[1]];
                     WVc = (const float*)d_in[i720[2]]; }
  else             { WVp = (const float*)d_in[i720[0]];
                     WVc = (const float*)d_in[i720[1]];
                     Wow = (const float*)d_in[i720[2]]; }
  float* out = (float*)d_out;                            // [2048] sampled ids (as float32)

  init_all<<<2048,256>>>(y, emb_raw, condW);
  fftnet_main<<<NCTA,512>>>(WVp, WVc, Wow, Wob, endw, endb, samples, out);
}

// round 15
// speedup vs baseline: 3.0068x; 1.3804x over previous
#include <cuda_runtime.h>
#include <cstdint>

#define FFTC 256
#define NL 11
#define TT 2048
#define NCTA 16
#define SPS 12                       // stages/step: s=0..10 layer-partial publishes; s=11 logits partials
#define NFLAGS (TT*SPS)
#define FSTRIDE 32                   // one 128B L2 line per flag (fallback fabric)
#define MEMCOLS 2047                 // sum of dilations 1+2+...+1024

// Persistent state (recomputed every kernel_launch for determinism)
__device__ float g_ring[(size_t)NCTA*MEMCOLS*FFTC]; // PRIVATE ring buffer per CTA
__device__ float g_cond[NL*16*FFTC];                // cond projections per (layer, frame)
__device__ float g_emb[256*FFTC];                   // tanh(emb_raw)
__device__ float g_part[12*NCTA*FFTC];              // per-layer (+logits) partial z vectors
__device__ unsigned g_flags[(size_t)NFLAGS*FSTRIDE];// fallback: monotone per-stage counters

// ---- fallback (R12) fabric: aggregated atomic counter + single-word acquire poll ----
__device__ __forceinline__ void poll_flag(int s, unsigned expect){
  const unsigned* p = g_flags + (size_t)s*FSTRIDE;
  unsigned v;
  do {
    asm volatile("ld.acquire.gpu.global.u32 %0, [%1];" : "=r"(v) : "l"(p) : "memory");
  } while (v < expect);
}
__device__ __forceinline__ void release_flag(int s){
  asm volatile("red.release.gpu.global.add.u32 [%0], %1;"
               :: "l"(g_flags + (size_t)s*FSTRIDE), "r"(1u) : "memory");
}

// 8-float (32B) weight load: read-only, keep resident in L2 (evict_last).
struct F8 { float f[8]; };
__device__ __forceinline__ F8 ldnc8(const float* p){
  unsigned long long a,b,c,d;
  asm volatile("ld.global.nc.L2::evict_last.v4.b64 {%0,%1,%2,%3}, [%4];"
               : "=l"(a), "=l"(b), "=l"(c), "=l"(d) : "l"(p));
  F8 r;
  r.f[0] = __uint_as_float((unsigned)(a));        r.f[1] = __uint_as_float((unsigned)(a>>32));
  r.f[2] = __uint_as_float((unsigned)(b));        r.f[3] = __uint_as_float((unsigned)(b>>32));
  r.f[4] = __uint_as_float((unsigned)(c));        r.f[5] = __uint_as_float((unsigned)(c>>32));
  r.f[6] = __uint_as_float((unsigned)(d));        r.f[7] = __uint_as_float((unsigned)(d>>32));
  return r;
}
// cross-CTA data: bypass L1 (L2 is the coherence point)
__device__ __forceinline__ float ldcg(const float* p){
  float v;
  asm volatile("ld.global.cg.f32 %0, [%1];" : "=f"(v) : "l"(p));
  return v;
}

__device__ __forceinline__ float dot8(const F8& w, const float* v, float p){
  #pragma unroll
  for (int k=0;k<8;k++) p = fmaf(w.f[k], v[k], p);
  return p;
}
__device__ __forceinline__ float red32(float p){
  #pragma unroll
  for (int k=16;k>0;k>>=1) p += __shfl_xor_sync(0xffffffffu, p, k);
  return p;
}

// ---------------- init + precompute fused ----------------
__global__ void init_all(const float* __restrict__ y,
                         const float* __restrict__ emb_raw,
                         const float* __restrict__ condW){
  const int b = blockIdx.x, tid = threadIdx.x;
  if (b < 256) {
    g_emb[b*256 + tid] = tanhf(emb_raw[b*256 + tid]);
  } else if (b < 256 + NL*16) {
    int b2 = b - 256;
    int j = b2 >> 4, f = b2 & 15;
    int row = j*256 + tid;
    float acc = 0.0f;
    #pragma unroll
    for (int c=0; c<80; c++) acc = fmaf(condW[row*80 + c], y[c*16 + f], acc);
    g_cond[(j*16 + f)*256 + tid] = acc;
  }
  size_t i = (size_t)b*blockDim.x + tid;
  size_t stride = (size_t)gridDim.x*blockDim.x;
  for (size_t k=i; k<(size_t)NCTA*MEMCOLS*FFTC; k+=stride) g_ring[k] = 0.0f;
  for (size_t k=i; k<(size_t)NFLAGS*FSTRIDE; k+=stride) g_flags[k] = 0u;
}

// ---------------- shared body: 16 CTAs x 512 threads ----------------
// CL=true : all 16 CTAs form ONE cluster; stage barrier = barrier.cluster arrive/wait
//           (arrive is per-thread release -> no pre-release __syncthreads needed).
// CL=false: R12 fabric (red.release + ld.acquire poll), the proven 48.2ms path.
template<bool CL>
__device__ __forceinline__ void fftnet_body(
  const float* __restrict__ WVp, const float* __restrict__ WVc,
  const float* __restrict__ Wow, const float* __restrict__ Wob,
  const float* __restrict__ endw, const float* __restrict__ endb,
  const float* __restrict__ samples, float* __restrict__ out)
{
  __shared__ __align__(16) float xs[FFTC];   // current x (identical in all CTAs)
  __shared__ __align__(16) float hs[16];     // this CTA's h rows
  __shared__ __align__(16) float lg[FFTC];   // logits (all CTAs)
  __shared__ __align__(16) float es[FFTC];   // staged emb row (sampler)
  __shared__ int s_sel;
  const int tid = threadIdx.x;
  const int blk = blockIdx.x;
  const int w = tid >> 5, lane = tid & 31;
  const int r = blk*16 + w;                  // h row owned by this warp
  const int zrow = tid >> 1;
  const int half = tid & 1;
  const int in0 = blk*16 + half*8;           // inner-dim base for partial z
  float* ring = g_ring + (size_t)blk*MEMCOLS*FFTC;

  if (tid < FFTC) xs[tid] = g_emb[127*FFTC + tid];
  __syncthreads();

  for (int t=0; t<TT; ++t){
    const int f = t >> 7;
    const int base = t*SPS;

    #pragma unroll 1
    for (int j=0; j<NL; ++j){
      const int col = ((1<<j) - 1) + (t & ((1<<j) - 1));
      // ---- ISSUE loads only; consume nothing until after the wait ----
      F8 wp = ldnc8(WVp + (size_t)(j*FFTC + r)*FFTC + lane*8);
      float mc[8];
      *(float4*)(mc)   = *(const float4*)(ring + col*FFTC + lane*8);
      *(float4*)(mc+4) = *(const float4*)(ring + col*FFTC + lane*8 + 4);
      F8 wc = ldnc8(WVc + (size_t)(j*FFTC + r)*FFTC + lane*8);
      F8 wo = ldnc8(Wow + (size_t)(j*FFTC + zrow)*FFTC + in0);
      float cnd = (lane==0) ? g_cond[(j*16 + f)*FFTC + r] : 0.0f;
      float wobp = (j>0 && tid<FFTC) ? Wob[(j-1)*FFTC + tid] : 0.0f;

      if (j > 0){
        if (CL) { asm volatile("barrier.cluster.wait.aligned;" ::: "memory"); }
        else    { if (tid==0) poll_flag(base + (j-1), NCTA); __syncthreads(); }
        if (tid < FFTC){
          float s1 = wobp;
          const float* gp = g_part + (j-1)*NCTA*FFTC + tid;
          #pragma unroll
          for (int k=0;k<NCTA;k++) s1 += ldcg(gp + k*FFTC);
          xs[tid] = fmaxf(s1 + xs[tid], 0.0f);        // x' = relu(z + b + x)
        }
        __syncthreads();
      }
      // ---- all math after the wait (loads have had the wait to land) ----
      float part = cnd;
      part = dot8(wp, mc, part);
      part = dot8(wc, xs + lane*8, part);
      part = red32(part);
      if (lane==0) hs[w] = fmaxf(part, 0.0f);
      __syncthreads();
      // partial z over this CTA's 16 h rows
      float pk = dot8(wo, hs + half*8, 0.0f);
      float oth = __shfl_xor_sync(0xffffffffu, pk, 1);
      float z = (half==0) ? (pk + oth) : (oth + pk);
      if (half==0) g_part[(j*NCTA + blk)*FFTC + zrow] = z;
      if (CL) { asm volatile("barrier.cluster.arrive.aligned;" ::: "memory"); }
      else    { __syncthreads(); if (tid==0) release_flag(base + j); }
      if (tid < FFTC) ring[col*FFTC + tid] = xs[tid]; // private, off the publish path
    }

    { // ---- logits: x' after layer 10, then partial endw slice ----
      F8 ew = ldnc8(endw + (size_t)zrow*FFTC + in0);
      float wobL = (tid<FFTC) ? Wob[10*FFTC + tid] : 0.0f;
      if (CL) { asm volatile("barrier.cluster.wait.aligned;" ::: "memory"); }
      else    { if (tid==0) poll_flag(base + 10, NCTA); __syncthreads(); }
      if (tid < FFTC){
        float s1 = wobL;
        const float* gp = g_part + 10*NCTA*FFTC + tid;
        #pragma unroll
        for (int k=0;k<NCTA;k++) s1 += ldcg(gp + k*FFTC);
        xs[tid] = fmaxf(s1 + xs[tid], 0.0f);
      }
      __syncthreads();
      float pk = dot8(ew, xs + in0, 0.0f);
      float oth = __shfl_xor_sync(0xffffffffu, pk, 1);
      float z = (half==0) ? (pk + oth) : (oth + pk);
      if (half==0) g_part[(11*NCTA + blk)*FFTC + zrow] = z;
      if (CL) { asm volatile("barrier.cluster.arrive.aligned;" ::: "memory"); }
      else    { __syncthreads(); if (tid==0) release_flag(base + 11); }
    }

    { // ---- sampler: ALL CTAs redundantly (deterministic); no broadcast sync ----
      float u = (tid < 32) ? samples[t] : 0.0f;       // prefetch before the wait
      if (CL) { asm volatile("barrier.cluster.wait.aligned;" ::: "memory"); }
      else    { if (tid==0) poll_flag(base + 11, NCTA); __syncthreads(); }
      if (tid < FFTC){
        float s1 = endb[tid];
        const float* gp = g_part + 11*NCTA*FFTC + tid;
        #pragma unroll
        for (int k=0;k<NCTA;k++) s1 += ldcg(gp + k*FFTC);
        lg[tid] = s1;                                 // C_SCALE == 1
      }
      __syncthreads();
      if (tid < 32){
        float4 va = *(const float4*)(lg + lane*8);
        float4 vb = *(const float4*)(lg + lane*8 + 4);
        float v[8] = {va.x,va.y,va.z,va.w,vb.x,vb.y,vb.z,vb.w};
        float m = v[0];
        #pragma unroll
        for (int k=1;k<8;k++) m = fmaxf(m, v[k]);
        #pragma unroll
        for (int k=16;k>0;k>>=1) m = fmaxf(m, __shfl_xor_sync(0xffffffffu, m, k));
        float e[8]; float sl = 0.0f;
        #pragma unroll
        for (int k=0;k<8;k++){ e[k] = expf(v[k] - m); sl += e[k]; }
        float tot = sl;
        #pragma unroll
        for (int k=16;k>0;k>>=1) tot += __shfl_xor_sync(0xffffffffu, tot, k);
        float cs[8]; float c = 0.0f;
        #pragma unroll
        for (int k=0;k<8;k++){ c += e[k] / tot; cs[k] = c; }
        float inc = c;
        #pragma unroll
        for (int k=1;k<32;k<<=1){ float o = __shfl_up_sync(0xffffffffu, inc, k); if (lane>=k) inc += o; }
        float off = __shfl_up_sync(0xffffffffu, inc, 1);
        if (lane == 0) off = 0.0f;
        int cand = 1<<30;
        #pragma unroll
        for (int k=0;k<8;k++) if (cand == (1<<30) && (off + cs[k]) > u) cand = lane*8 + k;
        #pragma unroll
        for (int k=16;k>0;k>>=1) cand = min(cand, __shfl_xor_sync(0xffffffffu, cand, k));
        int sel = (cand >= 256) ? 0 : cand;
        if (lane == 0){
          s_sel = sel;
          if (blk == 0) out[t] = (float)sel;
        }
        F8 er = ldnc8(g_emb + sel*FFTC + lane*8);
        #pragma unroll
        for (int k=0;k<8;k++) es[lane*8 + k] = er.f[k];
      }
      __syncthreads();
      if (tid < FFTC) xs[tid] = es[tid];              // next step's x0, locally
      __syncthreads();
    }
  }
}

__global__ void __cluster_dims__(NCTA,1,1) __launch_bounds__(512,1) fftnet_cluster(
  const float* __restrict__ WVp, const float* __restrict__ WVc,
  const float* __restrict__ Wow, const float* __restrict__ Wob,
  const float* __restrict__ endw, const float* __restrict__ endb,
  const float* __restrict__ samples, float* __restrict__ out)
{ fftnet_body<true>(WVp, WVc, Wow, Wob, endw, endb, samples, out); }

__global__ void __launch_bounds__(512,1) fftnet_flags(
  const float* __restrict__ WVp, const float* __restrict__ WVc,
  const float* __restrict__ Wow, const float* __restrict__ Wob,
  const float* __restrict__ endw, const float* __restrict__ endb,
  const float* __restrict__ samples, float* __restrict__ out)
{ fftnet_body<false>(WVp, WVc, Wow, Wob, endw, endb, samples, out); }

extern "C" void kernel_launch(void* const* d_in, const int* in_sizes, int n_in,
                              void* d_out, int out_size) {
  // ---- Robust input binding: identify tensors by element count, not position.
  int i1280=-1, i2048=-1, i225280=-1, i2816=-1, i256=-1;
  int i65536[2] = {-1,-1}; int n65536 = 0;
  int i720[3] = {-1,-1,-1}; int n720 = 0;
  for (int i=0;i<n_in;i++){
    switch (in_sizes[i]){
      case 1280:   i1280 = i; break;
      case 2048:   i2048 = i; break;
      case 225280: i225280 = i; break;
      case 2816:   i2816 = i; break;
      case 256:    i256 = i; break;
      case 65536:  if (n65536 < 2) i65536[n65536++] = i; break;
      case 720896: if (n720 < 3) i720[n720++] = i; break;
      default: break;
    }
  }
  if (i1280<0 || i2048<0 || i225280<0 || i2816<0 || i256<0 || n65536!=2 || n720!=3){
    i1280=0; i2048=1; i65536[0]=2; i225280=3; i720[0]=4; i720[1]=5; i720[2]=6;
    i2816=7; i65536[1]=8; i256=9;
  }
  const float* y        = (const float*)d_in[i1280];     // [80,16]
  const float* samples  = (const float*)d_in[i2048];     // [2048]
  const float* condW    = (const float*)d_in[i225280];   // [2816,80]
  const float* Wob      = (const float*)d_in[i2816];     // [11,256]
  const float* endb     = (const float*)d_in[i256];      // [256]
  const float* emb_raw  = (const float*)d_in[i65536[0]]; // [256,256]
  const float* endw     = (const float*)d_in[i65536[1]]; // [256,256]
  int before = 0;
  for (int k=0;k<3;k++) if (i720[k] < i2816) before++;
  const float *WVp, *WVc, *Wow;
  if (before == 0) { Wow = (const float*)d_in[i720[0]];
                     WVp = (const float*)d_in[i720[1]];
                     WVc = (const float*)d_in[i720[2]]; }
  else             { WVp = (const float*)d_in[i720[0]];
                     WVc = (const float*)d_in[i720[1]];
                     Wow = (const float*)d_in[i720[2]]; }
  float* out = (float*)d_out;                            // [2048] sampled ids (as float32)

  init_all<<<2048,256>>>(y, emb_raw, condW);

  // Prefer the HW cluster barrier (one 16-CTA cluster); fall back to the proven
  // L2-flag fabric if a 16-wide cluster isn't grantable on this part.
  cudaFuncSetAttribute(fftnet_cluster, cudaFuncAttributeNonPortableClusterSizeAllowed, 1);
  cudaLaunchConfig_t cfg = {};
  cfg.gridDim  = dim3(NCTA,1,1);
  cfg.blockDim = dim3(512,1,1);
  int maxC = 0;
  cudaOccupancyMaxPotentialClusterSize(&maxC, fftnet_cluster, &cfg);  // pure query, capture-safe
  if (maxC >= NCTA)
    fftnet_cluster<<<NCTA,512>>>(WVp, WVc, Wow, Wob, endw, endb, samples, out);
  else
    fftnet_flags<<<NCTA,512>>>(WVp, WVc, Wow, Wob, endw, endb, samples, out);
}

// round 16
// speedup vs baseline: 3.3953x; 1.1292x over previous
#include <cuda_runtime.h>
#include <cstdint>

#define FFTC 256
#define NL 11
#define TT 2048
#define NCTA 16
#define SPS 12                       // stages/step: s=0..10 layer partials; s=11 logits partials
#define NSL 12                       // mbarrier slots (parity handles step reuse)
#define NFLAGS (TT*SPS)
#define FSTRIDE 32                   // one 128B L2 line per flag (fallback fabric)
#define MEMCOLS 2047                 // sum of dilations 1+2+...+1024

// Persistent state (recomputed every kernel_launch for determinism)
__device__ float g_ring[(size_t)NCTA*MEMCOLS*FFTC]; // PRIVATE ring buffer per CTA
__device__ float g_cond[NL*16*FFTC];                // cond projections per (layer, frame)
__device__ float g_emb[256*FFTC];                   // tanh(emb_raw)
__device__ float g_part[12*NCTA*FFTC];              // per-layer (+logits) partial z vectors
__device__ unsigned g_flags[(size_t)NFLAGS*FSTRIDE];// fallback: monotone per-stage counters

// ---- fallback (R12) fabric ----
__device__ __forceinline__ void poll_flag(int s, unsigned expect){
  const unsigned* p = g_flags + (size_t)s*FSTRIDE;
  unsigned v;
  do {
    asm volatile("ld.acquire.gpu.global.u32 %0, [%1];" : "=r"(v) : "l"(p) : "memory");
  } while (v < expect);
}
__device__ __forceinline__ void release_flag(int s){
  asm volatile("red.release.gpu.global.add.u32 [%0], %1;"
               :: "l"(g_flags + (size_t)s*FSTRIDE), "r"(1u) : "memory");
}

// ---- cluster mbarrier fabric ----
__device__ __forceinline__ uint32_t smem_u32(const void* p){
  uint32_t a;
  asm("{ .reg .u64 t; cvta.to.shared.u64 t, %1; cvt.u32.u64 %0, t; }" : "=r"(a) : "l"(p));
  return a;
}
__device__ __forceinline__ uint32_t mapa32(uint32_t addr, uint32_t rank){
  uint32_t r; asm("mapa.shared::cluster.u32 %0, %1, %2;" : "=r"(r) : "r"(addr), "r"(rank));
  return r;
}
__device__ __forceinline__ void mb_init(uint32_t bar, uint32_t count){
  asm volatile("mbarrier.init.shared.b64 [%0], %1;" :: "r"(bar), "r"(count) : "memory");
}
__device__ __forceinline__ void mb_arrive_remote(uint32_t bar){
  asm volatile("mbarrier.arrive.release.cluster.shared::cluster.b64 _, [%0];"
               :: "r"(bar) : "memory");
}
__device__ __forceinline__ void mb_wait(uint32_t bar, uint32_t parity){
  uint32_t done;
  asm volatile("{\n\t.reg .pred P;\n\t"
    "mbarrier.try_wait.parity.acquire.cluster.shared::cta.b64 P, [%1], %2;\n\t"
    "selp.b32 %0, 1, 0, P;\n\t}"
    : "=r"(done) : "r"(bar), "r"(parity) : "memory");
  while (!done){
    asm volatile("{\n\t.reg .pred P;\n\t"
      "mbarrier.try_wait.parity.acquire.cluster.shared::cta.b64 P, [%1], %2, 0x989680;\n\t"
      "selp.b32 %0, 1, 0, P;\n\t}"
      : "=r"(done) : "r"(bar), "r"(parity) : "memory");
  }
}
__device__ __forceinline__ void cluster_sync_all(){
  asm volatile("barrier.cluster.arrive.aligned;" ::: "memory");
  asm volatile("barrier.cluster.wait.aligned;"   ::: "memory");
}

// 8-float (32B) weight load: read-only, keep resident in L2 (evict_last).
struct F8 { float f[8]; };
__device__ __forceinline__ F8 ldnc8(const float* p){
  unsigned long long a,b,c,d;
  asm volatile("ld.global.nc.L2::evict_last.v4.b64 {%0,%1,%2,%3}, [%4];"
               : "=l"(a), "=l"(b), "=l"(c), "=l"(d) : "l"(p));
  F8 r;
  r.f[0] = __uint_as_float((unsigned)(a));        r.f[1] = __uint_as_float((unsigned)(a>>32));
  r.f[2] = __uint_as_float((unsigned)(b));        r.f[3] = __uint_as_float((unsigned)(b>>32));
  r.f[4] = __uint_as_float((unsigned)(c));        r.f[5] = __uint_as_float((unsigned)(c>>32));
  r.f[6] = __uint_as_float((unsigned)(d));        r.f[7] = __uint_as_float((unsigned)(d>>32));
  return r;
}
__device__ __forceinline__ float ldcg(const float* p){
  float v;
  asm volatile("ld.global.cg.f32 %0, [%1];" : "=f"(v) : "l"(p));
  return v;
}

__device__ __forceinline__ float dot8(const F8& w, const float* v, float p){
  #pragma unroll
  for (int k=0;k<8;k++) p = fmaf(w.f[k], v[k], p);
  return p;
}
__device__ __forceinline__ float red32(float p){
  #pragma unroll
  for (int k=16;k>0;k>>=1) p += __shfl_xor_sync(0xffffffffu, p, k);
  return p;
}

// ---------------- init + precompute fused ----------------
__global__ void init_all(const float* __restrict__ y,
                         const float* __restrict__ emb_raw,
                         const float* __restrict__ condW){
  const int b = blockIdx.x, tid = threadIdx.x;
  if (b < 256) {
    g_emb[b*256 + tid] = tanhf(emb_raw[b*256 + tid]);
  } else if (b < 256 + NL*16) {
    int b2 = b - 256;
    int j = b2 >> 4, f = b2 & 15;
    int row = j*256 + tid;
    float acc = 0.0f;
    #pragma unroll
    for (int c=0; c<80; c++) acc = fmaf(condW[row*80 + c], y[c*16 + f], acc);
    g_cond[(j*16 + f)*256 + tid] = acc;
  }
  size_t i = (size_t)b*blockDim.x + tid;
  size_t stride = (size_t)gridDim.x*blockDim.x;
  for (size_t k=i; k<(size_t)NCTA*MEMCOLS*FFTC; k+=stride) g_ring[k] = 0.0f;
  for (size_t k=i; k<(size_t)NFLAGS*FSTRIDE; k+=stride) g_flags[k] = 0u;
}

// ---------------- shared body: 16 CTAs x 512 threads ----------------
// MB=true : cluster launch; per-stage smem mbarriers, 16 PARALLEL remote arrives
//           (lane k -> peer k), all-thread local try_wait (60-90cyc wake).
// MB=false: R12 L2-flag fabric (proven fallback).
template<bool MB>
__device__ __forceinline__ void fftnet_body(
  const float* __restrict__ WVp, const float* __restrict__ WVc,
  const float* __restrict__ Wow, const float* __restrict__ Wob,
  const float* __restrict__ endw, const float* __restrict__ endb,
  const float* __restrict__ samples, float* __restrict__ out)
{
  __shared__ __align__(16) float xs[FFTC];   // current x (identical in all CTAs)
  __shared__ __align__(16) float hs[16];     // this CTA's h rows
  __shared__ __align__(16) float lg[FFTC];   // logits (all CTAs)
  __shared__ __align__(16) float es[FFTC];   // staged emb row (sampler)
  __shared__ __align__(8) unsigned long long bars[NSL];
  __shared__ int s_sel;
  const int tid = threadIdx.x;
  const int blk = blockIdx.x;
  const int w = tid >> 5, lane = tid & 31;
  const int r = blk*16 + w;                  // h row owned by this warp
  const int zrow = tid >> 1;
  const int half = tid & 1;
  const int in0 = blk*16 + half*8;           // inner-dim base for partial z
  float* ring = g_ring + (size_t)blk*MEMCOLS*FFTC;

  uint32_t bar_u = 0, peer_bar = 0;
  if (MB){
    bar_u = smem_u32(bars);
    if (tid == 0){
      #pragma unroll
      for (int s=0;s<NSL;s++) mb_init(bar_u + s*8, NCTA);
    }
    __syncthreads();
    cluster_sync_all();                      // all slots initialized cluster-wide
    if (tid < NCTA) peer_bar = mapa32(bar_u, (uint32_t)tid);
  }

  if (tid < FFTC) xs[tid] = g_emb[127*FFTC + tid];
  __syncthreads();

  for (int t=0; t<TT; ++t){
    const int f = t >> 7;
    const int base = t*SPS;
    const uint32_t par = (uint32_t)(t & 1);

    #pragma unroll 1
    for (int j=0; j<NL; ++j){
      const int col = ((1<<j) - 1) + (t & ((1<<j) - 1));
      // ---- issue loads; compute x-independent terms pre-wait ----
      F8 wp = ldnc8(WVp + (size_t)(j*FFTC + r)*FFTC + lane*8);
      float mc[8];
      *(float4*)(mc)   = *(const float4*)(ring + col*FFTC + lane*8);
      *(float4*)(mc+4) = *(const float4*)(ring + col*FFTC + lane*8 + 4);
      F8 wc = ldnc8(WVc + (size_t)(j*FFTC + r)*FFTC + lane*8);
      F8 wo = ldnc8(Wow + (size_t)(j*FFTC + zrow)*FFTC + in0);
      float cnd = (lane==0) ? g_cond[(j*16 + f)*FFTC + r] : 0.0f;
      float wobp = (j>0 && tid<FFTC) ? Wob[(j-1)*FFTC + tid] : 0.0f;
      float part = cnd;
      part = dot8(wp, mc, part);              // past-tap dot: pre-wait (R12 order)

      if (j > 0){
        if (MB) { mb_wait(bar_u + (j-1)*8, par); }
        else    { if (tid==0) poll_flag(base + (j-1), NCTA); __syncthreads(); }
        if (tid < FFTC){
          float s1 = wobp;
          const float* gp = g_part + (j-1)*NCTA*FFTC + tid;
          #pragma unroll
          for (int k=0;k<NCTA;k++) s1 += ldcg(gp + k*FFTC);
          xs[tid] = fmaxf(s1 + xs[tid], 0.0f);        // x' = relu(z + b + x)
        }
        __syncthreads();
      }
      part = dot8(wc, xs + lane*8, part);
      part = red32(part);
      if (lane==0) hs[w] = fmaxf(part, 0.0f);
      __syncthreads();
      // partial z over this CTA's 16 h rows
      float pk = dot8(wo, hs + half*8, 0.0f);
      float oth = __shfl_xor_sync(0xffffffffu, pk, 1);
      float z = (half==0) ? (pk + oth) : (oth + pk);
      if (half==0) g_part[(j*NCTA + blk)*FFTC + zrow] = z;
      __syncthreads();                                // partial stores before publish
      if (MB) { if (tid < NCTA) mb_arrive_remote(peer_bar + j*8); }
      else    { if (tid==0) release_flag(base + j); }
      if (tid < FFTC) ring[col*FFTC + tid] = xs[tid]; // private, off the publish path
    }

    { // ---- logits: x' after layer 10, then partial endw slice ----
      F8 ew = ldnc8(endw + (size_t)zrow*FFTC + in0);
      float wobL = (tid<FFTC) ? Wob[10*FFTC + tid] : 0.0f;
      if (MB) { mb_wait(bar_u + 10*8, par); }
      else    { if (tid==0) poll_flag(base + 10, NCTA); __syncthreads(); }
      if (tid < FFTC){
        float s1 = wobL;
        const float* gp = g_part + 10*NCTA*FFTC + tid;
        #pragma unroll
        for (int k=0;k<NCTA;k++) s1 += ldcg(gp + k*FFTC);
        xs[tid] = fmaxf(s1 + xs[tid], 0.0f);
      }
      __syncthreads();
      float pk = dot8(ew, xs + in0, 0.0f);
      float oth = __shfl_xor_sync(0xffffffffu, pk, 1);
      float z = (half==0) ? (pk + oth) : (oth + pk);
      if (half==0) g_part[(11*NCTA + blk)*FFTC + zrow] = z;
      __syncthreads();
      if (MB) { if (tid < NCTA) mb_arrive_remote(peer_bar + 11*8); }
      else    { if (tid==0) release_flag(base + 11); }
    }

    { // ---- sampler: ALL CTAs redundantly (deterministic) ----
      float u = (tid < 32) ? samples[t] : 0.0f;
      if (MB) { mb_wait(bar_u + 11*8, par); }
      else    { if (tid==0) poll_flag(base + 11, NCTA); __syncthreads(); }
      if (tid < FFTC){
        float s1 = endb[tid];
        const float* gp = g_part + 11*NCTA*FFTC + tid;
        #pragma unroll
        for (int k=0;k<NCTA;k++) s1 += ldcg(gp + k*FFTC);
        lg[tid] = s1;                                 // C_SCALE == 1
      }
      __syncthreads();
      if (tid < 32){
        float4 va = *(const float4*)(lg + lane*8);
        float4 vb = *(const float4*)(lg + lane*8 + 4);
        float v[8] = {va.x,va.y,va.z,va.w,vb.x,vb.y,vb.z,vb.w};
        float m = v[0];
        #pragma unroll
        for (int k=1;k<8;k++) m = fmaxf(m, v[k]);
        #pragma unroll
        for (int k=16;k>0;k>>=1) m = fmaxf(m, __shfl_xor_sync(0xffffffffu, m, k));
        float e[8]; float sl = 0.0f;
        #pragma unroll
        for (int k=0;k<8;k++){ e[k] = expf(v[k] - m); sl += e[k]; }
        float tot = sl;
        #pragma unroll
        for (int k=16;k>0;k>>=1) tot += __shfl_xor_sync(0xffffffffu, tot, k);
        float cs[8]; float c = 0.0f;
        #pragma unroll
        for (int k=0;k<8;k++){ c += e[k] / tot; cs[k] = c; }
        float inc = c;
        #pragma unroll
        for (int k=1;k<32;k<<=1){ float o = __shfl_up_sync(0xffffffffu, inc, k); if (lane>=k) inc += o; }
        float off = __shfl_up_sync(0xffffffffu, inc, 1);
        if (lane == 0) off = 0.0f;
        int cand = 1<<30;
        #pragma unroll
        for (int k=0;k<8;k++) if (cand == (1<<30) && (off + cs[k]) > u) cand = lane*8 + k;
        #pragma unroll
        for (int k=16;k>0;k>>=1) cand = min(cand, __shfl_xor_sync(0xffffffffu, cand, k));
        int sel = (cand >= 256) ? 0 : cand;
        if (lane == 0){
          s_sel = sel;
          if (blk == 0) out[t] = (float)sel;
        }
        F8 er = ldnc8(g_emb + sel*FFTC + lane*8);
        #pragma unroll
        for (int k=0;k<8;k++) es[lane*8 + k] = er.f[k];
      }
      __syncthreads();
      if (tid < FFTC) xs[tid] = es[tid];              // next step's x0, locally
      __syncthreads();
    }
  }

  if (MB) cluster_sync_all();  // no CTA exits with peers' remote arrives in flight
}

__global__ void __cluster_dims__(NCTA,1,1) __launch_bounds__(512,1) fftnet_mbar(
  const float* __restrict__ WVp, const float* __restrict__ WVc,
  const float* __restrict__ Wow, const float* __restrict__ Wob,
  const float* __restrict__ endw, const float* __restrict__ endb,
  const float* __restrict__ samples, float* __restrict__ out)
{ fftnet_body<true>(WVp, WVc, Wow, Wob, endw, endb, samples, out); }

__global__ void __launch_bounds__(512,1) fftnet_flags(
  const float* __restrict__ WVp, const float* __restrict__ WVc,
  const float* __restrict__ Wow, const float* __restrict__ Wob,
  const float* __restrict__ endw, const float* __restrict__ endb,
  const float* __restrict__ samples, float* __restrict__ out)
{ fftnet_body<false>(WVp, WVc, Wow, Wob, endw, endb, samples, out); }

extern "C" void kernel_launch(void* const* d_in, const int* in_sizes, int n_in,
                              void* d_out, int out_size) {
  // ---- Robust input binding: identify tensors by element count, not position.
  int i1280=-1, i2048=-1, i225280=-1, i2816=-1, i256=-1;
  int i65536[2] = {-1,-1}; int n65536 = 0;
  int i720[3] = {-1,-1,-1}; int n720 = 0;
  for (int i=0;i<n_in;i++){
    switch (in_sizes[i]){
      case 1280:   i1280 = i; break;
      case 2048:   i2048 = i; break;
      case 225280: i225280 = i; break;
      case 2816:   i2816 = i; break;
      case 256:    i256 = i; break;
      case 65536:  if (n65536 < 2) i65536[n65536++] = i; break;
      case 720896: if (n720 < 3) i720[n720++] = i; break;
      default: break;
    }
  }
  if (i1280<0 || i2048<0 || i225280<0 || i2816<0 || i256<0 || n65536!=2 || n720!=3){
    i1280=0; i2048=1; i65536[0]=2; i225280=3; i720[0]=4; i720[1]=5; i720[2]=6;
    i2816=7; i65536[1]=8; i256=9;
  }
  const float* y        = (const float*)d_in[i1280];     // [80,16]
  const float* samples  = (const float*)d_in[i2048];     // [2048]
  const float* condW    = (const float*)d_in[i225280];   // [2816,80]
  const float* Wob      = (const float*)d_in[i2816];     // [11,256]
  const float* endb     = (const float*)d_in[i256];      // [256]
  const float* emb_raw  = (const float*)d_in[i65536[0]]; // [256,256]
  const float* endw     = (const float*)d_in[i65536[1]]; // [256,256]
  int before = 0;
  for (int k=0;k<3;k++) if (i720[k] < i2816) before++;
  const float *WVp, *WVc, *Wow;
  if (before == 0) { Wow = (const float*)d_in[i720[0]];
                     WVp = (const float*)d_in[i720[1]];
                     WVc = (const float*)d_in[i720[2]]; }
  else             { WVp = (const float*)d_in[i720[0]];
                     WVc = (const float*)d_in[i720[1]];
                     Wow = (const float*)d_in[i720[2]]; }
  float* out = (float*)d_out;                            // [2048] sampled ids (as float32)

  init_all<<<2048,256>>>(y, emb_raw, condW);

  cudaFuncSetAttribute(fftnet_mbar, cudaFuncAttributeNonPortableClusterSizeAllowed, 1);
  cudaLaunchConfig_t cfg = {};
  cfg.gridDim  = dim3(NCTA,1,1);
  cfg.blockDim = dim3(512,1,1);
  int maxC = 0;
  cudaOccupancyMaxPotentialClusterSize(&maxC, fftnet_mbar, &cfg);  // pure query, capture-safe
  if (maxC >= NCTA)
    fftnet_mbar<<<NCTA,512>>>(WVp, WVc, Wow, Wob, endw, endb, samples, out);
  else
    fftnet_flags<<<NCTA,512>>>(WVp, WVc, Wow, Wob, endw, endb, samples, out);
}